// round 2
// baseline (speedup 1.0000x reference)
#include <cuda_runtime.h>
#include <math.h>

// HorizonReward: UT rollout of cartpole with RBF policy.
// Single warp; lanes redundantly compute the serial chain (keeps everything
// in registers, no smem, no block syncs); 50 RBFs split 2-per-lane with a
// butterfly reduction for the policy output.
//
// Key algebraic collapse (exact in real arithmetic):
//   - the 81-point "expanded" UT reduces to Cov_w(next_means) +
//     (PROC_NOISE*DT + JITTER)*I  (symmetric offsets kill all cross terms)
//   - _gen_sigma then adds another JITTER*I  -> DIAG_ADD = 5.02e-4
//   - weights are always the fixed UT weights (0.2, 0.1 x 8)

__global__ __launch_bounds__(32, 1)
void horizon_reward_kernel(const float* __restrict__ p, float* __restrict__ out)
{
    const int lane = threadIdx.x & 31;

    // ---- load policy params into registers (2 RBFs per lane) ----
    // layout: p[0:50]=w ; p[50:250]=mu[k][j] (k*50+j) ; p[250:750]=sp[j][t] (j*10+t)
    float wA = 0.f, wB = 0.f;
    float muA[4], muB[4] = {0.f, 0.f, 0.f, 0.f};
    float LA[10], LB[10];
    #pragma unroll
    for (int t = 0; t < 10; ++t) LB[t] = 0.f;
    {
        const int j = lane;              // always < 50
        wA = p[j];
        #pragma unroll
        for (int k = 0; k < 4; ++k) muA[k] = p[50 + k * 50 + j];
        #pragma unroll
        for (int t = 0; t < 10; ++t) LA[t] = p[250 + j * 10 + t];
        const int j2 = lane + 32;
        if (j2 < 50) {
            wB = p[j2];
            #pragma unroll
            for (int k = 0; k < 4; ++k) muB[k] = p[50 + k * 50 + j2];
            #pragma unroll
            for (int t = 0; t < 10; ++t) LB[t] = p[250 + j2 * 10 + t];
        }
    }

    const float DT = 0.05f;
    const float W0 = 0.2f;        // kappa/(n+kappa), kappa=1, n=4
    const float WI = 0.1f;        // 1/(2(n+kappa))
    const float R5 = sqrtf(5.0f); // sqrt(n+kappa)
    const float DIAG_ADD = 0.01f * 0.05f + 2.0f * 1e-6f; // proc noise + 2*jitter

    // ---- initial sigma points: x0 ± sqrt(5)*sqrt(jitter)*e_j ----
    float st[9][4];
    const float x0c[4] = {0.f, 0.f, 0.1f, 0.f};
    const float r0 = R5 * 1e-3f;
    #pragma unroll
    for (int i = 0; i < 9; ++i) {
        #pragma unroll
        for (int k = 0; k < 4; ++k) st[i][k] = x0c[k];
    }
    #pragma unroll
    for (int k = 0; k < 4; ++k) { st[1 + k][k] += r0; st[5 + k][k] -= r0; }

    float reward = 0.f;

    for (int t = 0; t < 60; ++t) {
        // ---- weighted mean of sigma points ----
        float mean[4];
        #pragma unroll
        for (int k = 0; k < 4; ++k) {
            float s = st[1][k];
            #pragma unroll
            for (int i = 2; i < 9; ++i) s += st[i][k];
            mean[k] = W0 * st[0][k] + WI * s;
        }

        // ---- policy: sum_j w_j * exp(-||L_j^T (mean - mu_j)||^2) ----
        float acc;
        {
            float d0 = mean[0] - muA[0], d1 = mean[1] - muA[1];
            float d2 = mean[2] - muA[2], d3 = mean[3] - muA[3];
            float l0 = LA[0] * d0 + LA[4] * d1 + LA[5] * d2 + LA[7] * d3;
            float l1 = LA[1] * d1 + LA[6] * d2 + LA[8] * d3;
            float l2 = LA[2] * d2 + LA[9] * d3;
            float l3 = LA[3] * d3;
            float q = l0 * l0 + l1 * l1 + l2 * l2 + l3 * l3;
            acc = wA * expf(-q);
        }
        {
            float d0 = mean[0] - muB[0], d1 = mean[1] - muB[1];
            float d2 = mean[2] - muB[2], d3 = mean[3] - muB[3];
            float l0 = LB[0] * d0 + LB[4] * d1 + LB[5] * d2 + LB[7] * d3;
            float l1 = LB[1] * d1 + LB[6] * d2 + LB[8] * d3;
            float l2 = LB[2] * d2 + LB[9] * d3;
            float l3 = LB[3] * d3;
            float q = l0 * l0 + l1 * l1 + l2 * l2 + l3 * l3;
            acc += wB * expf(-q);
        }
        #pragma unroll
        for (int o = 16; o > 0; o >>= 1)
            acc += __shfl_xor_sync(0xffffffffu, acc, o);
        const float u = fminf(fmaxf(acc, -10.f), 10.f);

        // ---- cartpole dynamics on the 9 sigma points (shared scalar u) ----
        float nx[9][4];
        #pragma unroll
        for (int i = 0; i < 9; ++i) {
            float pos = st[i][0], vel = st[i][1], th = st[i][2], thd = st[i][3];
            float s = sinf(th), c = cosf(th);
            float temp = (u + 0.05f * thd * thd * s) * (1.0f / 1.1f);
            float denom = 0.5f * (4.0f / 3.0f - (0.1f / 1.1f) * c * c);
            float thacc = (9.8f * s - c * temp) / denom;
            float xacc = temp - (0.05f / 1.1f) * thacc * c;
            nx[i][0] = pos + DT * vel;
            nx[i][1] = vel + DT * xacc;
            nx[i][2] = th + DT * thd;
            nx[i][3] = thd + DT * thacc;
        }

        // ---- new mean ----
        float m[4];
        #pragma unroll
        for (int k = 0; k < 4; ++k) {
            float s = nx[1][k];
            #pragma unroll
            for (int i = 2; i < 9; ++i) s += nx[i][k];
            m[k] = W0 * nx[0][k] + WI * s;
        }

        // ---- covariance (analytic collapse of the 81-point UT expansion) ----
        float c00 = 0, c10 = 0, c11 = 0, c20 = 0, c21 = 0, c22 = 0;
        float c30 = 0, c31 = 0, c32 = 0, c33 = 0;
        #pragma unroll
        for (int i = 0; i < 9; ++i) {
            const float w = (i == 0) ? W0 : WI;
            float d0 = nx[i][0] - m[0], d1 = nx[i][1] - m[1];
            float d2 = nx[i][2] - m[2], d3 = nx[i][3] - m[3];
            c00 += w * d0 * d0;
            c10 += w * d1 * d0; c11 += w * d1 * d1;
            c20 += w * d2 * d0; c21 += w * d2 * d1; c22 += w * d2 * d2;
            c30 += w * d3 * d0; c31 += w * d3 * d1; c32 += w * d3 * d2;
            c33 += w * d3 * d3;
        }
        c00 += DIAG_ADD; c11 += DIAG_ADD; c22 += DIAG_ADD; c33 += DIAG_ADD;

        // ---- 4x4 Cholesky (lower) ----
        const float S00 = sqrtf(c00);
        const float i0 = 1.0f / S00;
        const float S10 = c10 * i0, S20 = c20 * i0, S30 = c30 * i0;
        const float S11 = sqrtf(c11 - S10 * S10);
        const float i1 = 1.0f / S11;
        const float S21 = (c21 - S20 * S10) * i1;
        const float S31 = (c31 - S30 * S10) * i1;
        const float S22 = sqrtf(c22 - S20 * S20 - S21 * S21);
        const float i2 = 1.0f / S22;
        const float S32 = (c32 - S30 * S20 - S31 * S21) * i2;
        const float S33 = sqrtf(c33 - S30 * S30 - S31 * S31 - S32 * S32);

        // ---- regenerate sigma points: m, m ± sqrt(5)*S[:,j] ----
        const float col[4][4] = {
            {S00, S10, S20, S30},
            {0.f, S11, S21, S31},
            {0.f, 0.f, S22, S32},
            {0.f, 0.f, 0.f, S33}};
        #pragma unroll
        for (int k = 0; k < 4; ++k) st[0][k] = m[k];
        #pragma unroll
        for (int j = 0; j < 4; ++j) {
            #pragma unroll
            for (int k = 0; k < 4; ++k) {
                const float off = R5 * col[j][k];
                st[1 + j][k] = m[k] + off;
                st[5 + j][k] = m[k] - off;
            }
        }

        // ---- reward on the NEW sigma points ----
        float csum = 0.f;
        #pragma unroll
        for (int i = 0; i < 9; ++i) {
            const float w = (i == 0) ? W0 : WI;
            const float cst = st[i][0] * st[i][0] + st[i][1] * st[i][1] +
                              10.f * st[i][2] * st[i][2] + st[i][3] * st[i][3];
            csum += w * cst;
        }
        reward -= csum;
    }

    if (lane == 0) out[0] = reward;
}

extern "C" void kernel_launch(void* const* d_in, const int* in_sizes, int n_in,
                              void* d_out, int out_size) {
    (void)in_sizes; (void)n_in; (void)out_size;
    horizon_reward_kernel<<<1, 32>>>((const float*)d_in[0], (float*)d_out);
}

// round 3
// speedup vs baseline: 2.9745x; 2.9745x over previous
#include <cuda_runtime.h>
#include <math.h>

// HorizonReward: UT rollout of cartpole with RBF policy.
// Single warp; lanes redundantly compute the serial chain (all register-
// resident, no smem, no block syncs); 50 RBFs split 2-per-lane with a
// butterfly reduction for the policy output.
//
// R3: fast-math intrinsics (__expf/__sinf/__cosf/__fdividef/rsqrtf) to cut
// the software-transcendental instruction streams; chol(5C)=sqrt5*chol(C)
// folding so sigma regeneration needs no sqrt(5) scaling.

__global__ __launch_bounds__(32, 1)
void horizon_reward_kernel(const float* __restrict__ p, float* __restrict__ out)
{
    const int lane = threadIdx.x & 31;

    // ---- load policy params into registers (2 RBFs per lane) ----
    // layout: p[0:50]=w ; p[50:250]=mu[k][j] (k*50+j) ; p[250:750]=sp[j][t] (j*10+t)
    float wA = 0.f, wB = 0.f;
    float muA[4], muB[4] = {0.f, 0.f, 0.f, 0.f};
    float LA[10], LB[10];
    #pragma unroll
    for (int t = 0; t < 10; ++t) LB[t] = 0.f;
    {
        const int j = lane;              // always < 50
        wA = p[j];
        #pragma unroll
        for (int k = 0; k < 4; ++k) muA[k] = p[50 + k * 50 + j];
        #pragma unroll
        for (int t = 0; t < 10; ++t) LA[t] = p[250 + j * 10 + t];
        const int j2 = lane + 32;
        if (j2 < 50) {
            wB = p[j2];
            #pragma unroll
            for (int k = 0; k < 4; ++k) muB[k] = p[50 + k * 50 + j2];
            #pragma unroll
            for (int t = 0; t < 10; ++t) LB[t] = p[250 + j2 * 10 + t];
        }
    }

    const float DT = 0.05f;
    const float W0 = 0.2f;         // kappa/(n+kappa)
    const float WI = 0.1f;         // 1/(2(n+kappa))
    const float R5 = 2.23606797749979f;            // sqrt(5)
    // covariance accumulated PRE-SCALED by 5 (=R5^2), so chol gives R5*S:
    const float CW0 = 1.0f;        // 5*W0
    const float CWI = 0.5f;        // 5*WI
    const float DIAG_ADD5 = 5.0f * (0.01f * 0.05f + 2.0f * 1e-6f); // 5*(proc+2*jitter)

    // ---- initial sigma points: x0 ± sqrt(5)*sqrt(jitter)*e_j ----
    float st[9][4];
    const float x0c[4] = {0.f, 0.f, 0.1f, 0.f};
    const float r0i = R5 * 1e-3f;
    #pragma unroll
    for (int i = 0; i < 9; ++i) {
        #pragma unroll
        for (int k = 0; k < 4; ++k) st[i][k] = x0c[k];
    }
    #pragma unroll
    for (int k = 0; k < 4; ++k) { st[1 + k][k] += r0i; st[5 + k][k] -= r0i; }

    float reward = 0.f;

    for (int t = 0; t < 60; ++t) {
        // ---- weighted mean of sigma points ----
        float mean[4];
        #pragma unroll
        for (int k = 0; k < 4; ++k) {
            float s = st[1][k];
            #pragma unroll
            for (int i = 2; i < 9; ++i) s += st[i][k];
            mean[k] = W0 * st[0][k] + WI * s;
        }

        // ---- policy: sum_j w_j * exp(-||L_j^T (mean - mu_j)||^2) ----
        float acc;
        {
            float d0 = mean[0] - muA[0], d1 = mean[1] - muA[1];
            float d2 = mean[2] - muA[2], d3 = mean[3] - muA[3];
            float l0 = LA[0] * d0 + LA[4] * d1 + LA[5] * d2 + LA[7] * d3;
            float l1 = LA[1] * d1 + LA[6] * d2 + LA[8] * d3;
            float l2 = LA[2] * d2 + LA[9] * d3;
            float l3 = LA[3] * d3;
            float q = l0 * l0 + l1 * l1 + l2 * l2 + l3 * l3;
            acc = wA * __expf(-q);
        }
        {
            float d0 = mean[0] - muB[0], d1 = mean[1] - muB[1];
            float d2 = mean[2] - muB[2], d3 = mean[3] - muB[3];
            float l0 = LB[0] * d0 + LB[4] * d1 + LB[5] * d2 + LB[7] * d3;
            float l1 = LB[1] * d1 + LB[6] * d2 + LB[8] * d3;
            float l2 = LB[2] * d2 + LB[9] * d3;
            float l3 = LB[3] * d3;
            float q = l0 * l0 + l1 * l1 + l2 * l2 + l3 * l3;
            acc += wB * __expf(-q);
        }
        #pragma unroll
        for (int o = 16; o > 0; o >>= 1)
            acc += __shfl_xor_sync(0xffffffffu, acc, o);
        const float u = fminf(fmaxf(acc, -10.f), 10.f);
        const float u_div = u * (1.0f / 1.1f);

        // ---- cartpole dynamics on the 9 sigma points (shared scalar u) ----
        float nx[9][4];
        #pragma unroll
        for (int i = 0; i < 9; ++i) {
            float pos = st[i][0], vel = st[i][1], th = st[i][2], thd = st[i][3];
            float s = __sinf(th), c = __cosf(th);
            float temp = u_div + (0.05f / 1.1f) * thd * thd * s;
            float denom = 0.5f * (4.0f / 3.0f) - (0.5f * 0.1f / 1.1f) * c * c;
            float thacc = __fdividef(9.8f * s - c * temp, denom);
            float xacc = temp - (0.05f / 1.1f) * thacc * c;
            nx[i][0] = pos + DT * vel;
            nx[i][1] = vel + DT * xacc;
            nx[i][2] = th + DT * thd;
            nx[i][3] = thd + DT * thacc;
        }

        // ---- new mean ----
        float m[4];
        #pragma unroll
        for (int k = 0; k < 4; ++k) {
            float s = nx[1][k];
            #pragma unroll
            for (int i = 2; i < 9; ++i) s += nx[i][k];
            m[k] = W0 * nx[0][k] + WI * s;
        }

        // ---- covariance x5 (analytic collapse of the 81-point UT expansion,
        //      pre-scaled by 5 so chol() directly yields sqrt(5)*S) ----
        float c00, c10, c11, c20, c21, c22, c30, c31, c32, c33;
        {
            float d0 = nx[0][0] - m[0], d1 = nx[0][1] - m[1];
            float d2 = nx[0][2] - m[2], d3 = nx[0][3] - m[3];
            // CW0 = 1.0 -> no weight multiply for point 0
            c00 = d0 * d0;
            c10 = d1 * d0; c11 = d1 * d1;
            c20 = d2 * d0; c21 = d2 * d1; c22 = d2 * d2;
            c30 = d3 * d0; c31 = d3 * d1; c32 = d3 * d2; c33 = d3 * d3;
        }
        {
            float a00 = 0, a10 = 0, a11 = 0, a20 = 0, a21 = 0, a22 = 0;
            float a30 = 0, a31 = 0, a32 = 0, a33 = 0;
            #pragma unroll
            for (int i = 1; i < 9; ++i) {
                float d0 = nx[i][0] - m[0], d1 = nx[i][1] - m[1];
                float d2 = nx[i][2] - m[2], d3 = nx[i][3] - m[3];
                a00 += d0 * d0;
                a10 += d1 * d0; a11 += d1 * d1;
                a20 += d2 * d0; a21 += d2 * d1; a22 += d2 * d2;
                a30 += d3 * d0; a31 += d3 * d1; a32 += d3 * d2; a33 += d3 * d3;
            }
            c00 += CWI * a00;
            c10 += CWI * a10; c11 += CWI * a11;
            c20 += CWI * a20; c21 += CWI * a21; c22 += CWI * a22;
            c30 += CWI * a30; c31 += CWI * a31; c32 += CWI * a32;
            c33 += CWI * a33;
        }
        c00 += DIAG_ADD5; c11 += DIAG_ADD5; c22 += DIAG_ADD5; c33 += DIAG_ADD5;

        // ---- 4x4 Cholesky (lower) via rsqrt; result is already sqrt(5)*S ----
        const float r0 = rsqrtf(c00);
        const float S00 = c00 * r0;
        const float S10 = c10 * r0, S20 = c20 * r0, S30 = c30 * r0;
        const float a11c = c11 - S10 * S10;
        const float r1 = rsqrtf(a11c);
        const float S11 = a11c * r1;
        const float S21 = (c21 - S20 * S10) * r1;
        const float S31 = (c31 - S30 * S10) * r1;
        const float a22c = c22 - S20 * S20 - S21 * S21;
        const float r2 = rsqrtf(a22c);
        const float S22 = a22c * r2;
        const float S32 = (c32 - S30 * S20 - S31 * S21) * r2;
        const float a33c = c33 - S30 * S30 - S31 * S31 - S32 * S32;
        const float S33 = a33c * rsqrtf(a33c);

        // ---- regenerate sigma points: m, m ± (sqrt(5)*S)[:,j] ----
        #pragma unroll
        for (int k = 0; k < 4; ++k) st[0][k] = m[k];
        st[1][0] = m[0] + S00; st[5][0] = m[0] - S00;
        st[1][1] = m[1] + S10; st[5][1] = m[1] - S10;
        st[1][2] = m[2] + S20; st[5][2] = m[2] - S20;
        st[1][3] = m[3] + S30; st[5][3] = m[3] - S30;
        st[2][0] = m[0];       st[6][0] = m[0];
        st[2][1] = m[1] + S11; st[6][1] = m[1] - S11;
        st[2][2] = m[2] + S21; st[6][2] = m[2] - S21;
        st[2][3] = m[3] + S31; st[6][3] = m[3] - S31;
        st[3][0] = m[0];       st[7][0] = m[0];
        st[3][1] = m[1];       st[7][1] = m[1];
        st[3][2] = m[2] + S22; st[7][2] = m[2] - S22;
        st[3][3] = m[3] + S32; st[7][3] = m[3] - S32;
        st[4][0] = m[0];       st[8][0] = m[0];
        st[4][1] = m[1];       st[8][1] = m[1];
        st[4][2] = m[2];       st[8][2] = m[2];
        st[4][3] = m[3] + S33; st[8][3] = m[3] - S33;

        // ---- reward on the NEW sigma points ----
        float csum0, csumI = 0.f;
        csum0 = st[0][0] * st[0][0] + st[0][1] * st[0][1] +
                10.f * st[0][2] * st[0][2] + st[0][3] * st[0][3];
        #pragma unroll
        for (int i = 1; i < 9; ++i) {
            csumI += st[i][0] * st[i][0] + st[i][1] * st[i][1] +
                     10.f * st[i][2] * st[i][2] + st[i][3] * st[i][3];
        }
        reward -= W0 * csum0 + WI * csumI;
    }

    if (lane == 0) out[0] = reward;
}

extern "C" void kernel_launch(void* const* d_in, const int* in_sizes, int n_in,
                              void* d_out, int out_size) {
    (void)in_sizes; (void)n_in; (void)out_size;
    horizon_reward_kernel<<<1, 32>>>((const float*)d_in[0], (float*)d_out);
}

// round 4
// speedup vs baseline: 5.8765x; 1.9756x over previous
#include <cuda_runtime.h>
#include <math.h>

// HorizonReward: UT rollout of cartpole with RBF policy — fully collapsed form.
// State per step: mean m[4] + scaled Cholesky factor Sc = sqrt(5)*chol(C)
// (10 lower-tri entries). Sigma points never materialized:
//   - mean of regenerated points == m (symmetry)          -> policy input free
//   - linear coords (pos, th) propagate analytically      -> A_j, C_j deviations
//   - reward = m^T Q m + 0.2 * trace(Q * ScSc^T)          -> closed form
// Covariance is accumulated pre-scaled by 5 so chol() directly yields the
// next Sc. Single warp; 50 RBFs split 2/lane + butterfly reduction.

__device__ __forceinline__ float policy_u(
    const float m0, const float m1, const float m2, const float m3,
    const float wA, const float* muA, const float* LA,
    const float wB, const float* muB, const float* LB)
{
    float acc;
    {
        float d0 = m0 - muA[0], d1 = m1 - muA[1], d2 = m2 - muA[2], d3 = m3 - muA[3];
        float l0 = LA[0] * d0 + LA[4] * d1 + LA[5] * d2 + LA[7] * d3;
        float l1 = LA[1] * d1 + LA[6] * d2 + LA[8] * d3;
        float l2 = LA[2] * d2 + LA[9] * d3;
        float l3 = LA[3] * d3;
        acc = wA * __expf(-(l0 * l0 + l1 * l1 + l2 * l2 + l3 * l3));
    }
    {
        float d0 = m0 - muB[0], d1 = m1 - muB[1], d2 = m2 - muB[2], d3 = m3 - muB[3];
        float l0 = LB[0] * d0 + LB[4] * d1 + LB[5] * d2 + LB[7] * d3;
        float l1 = LB[1] * d1 + LB[6] * d2 + LB[8] * d3;
        float l2 = LB[2] * d2 + LB[9] * d3;
        float l3 = LB[3] * d3;
        acc += wB * __expf(-(l0 * l0 + l1 * l1 + l2 * l2 + l3 * l3));
    }
    #pragma unroll
    for (int o = 16; o > 0; o >>= 1)
        acc += __shfl_xor_sync(0xffffffffu, acc, o);
    return fminf(fmaxf(acc, -10.f), 10.f);
}

__global__ __launch_bounds__(32, 1)
void horizon_reward_kernel(const float* __restrict__ p, float* __restrict__ out)
{
    const int lane = threadIdx.x & 31;

    // ---- policy params into registers (2 RBFs per lane) ----
    float wA = 0.f, wB = 0.f;
    float muA[4], muB[4] = {0.f, 0.f, 0.f, 0.f};
    float LA[10], LB[10];
    #pragma unroll
    for (int t = 0; t < 10; ++t) LB[t] = 0.f;
    {
        const int j = lane;
        wA = p[j];
        #pragma unroll
        for (int k = 0; k < 4; ++k) muA[k] = p[50 + k * 50 + j];
        #pragma unroll
        for (int t = 0; t < 10; ++t) LA[t] = p[250 + j * 10 + t];
        const int j2 = lane + 32;
        if (j2 < 50) {
            wB = p[j2];
            #pragma unroll
            for (int k = 0; k < 4; ++k) muB[k] = p[50 + k * 50 + j2];
            #pragma unroll
            for (int t = 0; t < 10; ++t) LB[t] = p[250 + j2 * 10 + t];
        }
    }

    const float DT = 0.05f;
    const float W0 = 0.2f, WI = 0.1f;
    const float K1 = 0.05f / 1.1f;            // pml/mt
    const float K3 = 0.5f * (4.0f / 3.0f);    // len * 4/3
    const float K2 = 0.5f * 0.1f / 1.1f;      // len * mp/mt
    const float DIAG_ADD5 = 5.0f * (0.01f * 0.05f + 2.0f * 1e-6f);

    // ---- state: mean + scaled Cholesky (lower tri, col-major with zeros) ----
    float m0 = 0.f, m1 = 0.f, m2 = 0.1f, m3 = 0.f;
    const float r0i = 2.23606797749979f * 1e-3f;   // sqrt(5)*sqrt(jitter)
    float S00 = r0i, S10 = 0.f, S20 = 0.f, S30 = 0.f;
    float S11 = r0i, S21 = 0.f, S31 = 0.f;
    float S22 = r0i, S32 = 0.f;
    float S33 = r0i;

    float u = policy_u(m0, m1, m2, m3, wA, muA, LA, wB, muB, LB);
    float reward = 0.f;

    for (int t = 0; t < 60; ++t) {
        const float u_div = u * (1.0f / 1.1f);

        // sigma-point th/thd (pos/vel never needed pointwise):
        // idx: 0=center, 1..4 = +col_j, 5..8 = -col_j.  col3[2]=0 -> pts 4,8
        // share th with center.
        float th[9], thd[9];
        th[0] = m2;                 thd[0] = m3;
        th[1] = m2 + S20;           thd[1] = m3 + S30;
        th[2] = m2 + S21;           thd[2] = m3 + S31;
        th[3] = m2 + S22;           thd[3] = m3 + S32;
        th[4] = m2;                 thd[4] = m3 + S33;
        th[5] = m2 - S20;           thd[5] = m3 - S30;
        th[6] = m2 - S21;           thd[6] = m3 - S31;
        th[7] = m2 - S22;           thd[7] = m3 - S32;
        th[8] = m2;                 thd[8] = m3 - S33;

        // 7 unique th values -> 7 sincos / 7 reciprocal-denoms
        float sn[9], cs[9], rd[9];
        #pragma unroll
        for (int i = 0; i < 8; ++i) {       // 0..7 unique (4 dup of 0)
            if (i == 4) continue;
            float s = __sinf(th[i]), c = __cosf(th[i]);
            sn[i] = s; cs[i] = c;
            rd[i] = __fdividef(1.0f, K3 - K2 * c * c);
        }
        sn[4] = sn[0]; cs[4] = cs[0]; rd[4] = rd[0];
        sn[8] = sn[0]; cs[8] = cs[0]; rd[8] = rd[0];

        float xacc[9], thacc[9];
        #pragma unroll
        for (int i = 0; i < 9; ++i) {
            float s = sn[i], c = cs[i];
            float temp = fmaf(K1 * thd[i] * thd[i], s, u_div);
            float ta = (fmaf(-c, temp, 9.8f * s)) * rd[i];
            thacc[i] = ta;
            xacc[i] = fmaf(-K1, ta * c, temp);
        }

        // weighted means of accelerations
        float xs = xacc[1], ts = thacc[1];
        #pragma unroll
        for (int i = 2; i < 9; ++i) { xs += xacc[i]; ts += thacc[i]; }
        const float xbar = fmaf(W0, xacc[0], WI * xs);
        const float tbar = fmaf(W0, thacc[0], WI * ts);

        // next mean (linear coords analytic)
        const float n0 = fmaf(DT, m1, m0);
        const float n1 = fmaf(DT, xbar, m1);
        const float n2 = fmaf(DT, m3, m2);
        const float n3 = fmaf(DT, tbar, m3);

        // acceleration deviations
        float v1[9], v3[9];
        #pragma unroll
        for (int i = 0; i < 9; ++i) { v1[i] = xacc[i] - xbar; v3[i] = thacc[i] - tbar; }

        // coordinate deviations of next points from next mean (pre-scaled x5):
        // linear coords: +/-A_j, +/-C_j ; nonlinear: B (coord1), D (coord3).
        const float A0 = fmaf(DT, S10, S00);
        const float A1 = DT * S11;
        const float C0 = fmaf(DT, S30, S20);
        const float C1 = fmaf(DT, S31, S21);
        const float C2 = fmaf(DT, S32, S22);
        const float C3 = DT * S33;

        const float B0c = DT * v1[0];
        const float Bp0 = fmaf(DT, v1[1], S10), Bm0 = fmaf(DT, v1[5], -S10);
        const float Bp1 = fmaf(DT, v1[2], S11), Bm1 = fmaf(DT, v1[6], -S11);
        const float Bp2 = DT * v1[3],           Bm2 = DT * v1[7];
        const float Bp3 = DT * v1[4],           Bm3 = DT * v1[8];

        const float D0c = DT * v3[0];
        const float Dp0 = fmaf(DT, v3[1], S30), Dm0 = fmaf(DT, v3[5], -S30);
        const float Dp1 = fmaf(DT, v3[2], S31), Dm1 = fmaf(DT, v3[6], -S31);
        const float Dp2 = fmaf(DT, v3[3], S32), Dm2 = fmaf(DT, v3[7], -S32);
        const float Dp3 = fmaf(DT, v3[4], S33), Dm3 = fmaf(DT, v3[8], -S33);

        // covariance (x5), exploiting symmetry: pairs contribute +/-A, +/-C
        float c00 = fmaf(A1, A1, A0 * A0);
        float c20 = fmaf(A1, C1, A0 * C0);
        float c22 = fmaf(C3, C3, fmaf(C2, C2, fmaf(C1, C1, C0 * C0)));

        const float gB0 = Bp0 - Bm0, gB1 = Bp1 - Bm1, gB2 = Bp2 - Bm2, gB3 = Bp3 - Bm3;
        const float gD0 = Dp0 - Dm0, gD1 = Dp1 - Dm1, gD2 = Dp2 - Dm2, gD3 = Dp3 - Dm3;

        float c10 = 0.5f * fmaf(A1, gB1, A0 * gB0);
        float c30 = 0.5f * fmaf(A1, gD1, A0 * gD0);
        float c21 = 0.5f * fmaf(C3, gB3, fmaf(C2, gB2, fmaf(C1, gB1, C0 * gB0)));
        float c32 = 0.5f * fmaf(C3, gD3, fmaf(C2, gD2, fmaf(C1, gD1, C0 * gD0)));

        float sB = Bp0 * Bp0;
        sB = fmaf(Bp1, Bp1, sB); sB = fmaf(Bp2, Bp2, sB); sB = fmaf(Bp3, Bp3, sB);
        sB = fmaf(Bm0, Bm0, sB); sB = fmaf(Bm1, Bm1, sB);
        sB = fmaf(Bm2, Bm2, sB); sB = fmaf(Bm3, Bm3, sB);
        float c11 = fmaf(0.5f, sB, B0c * B0c);

        float sD = Dp0 * Dp0;
        sD = fmaf(Dp1, Dp1, sD); sD = fmaf(Dp2, Dp2, sD); sD = fmaf(Dp3, Dp3, sD);
        sD = fmaf(Dm0, Dm0, sD); sD = fmaf(Dm1, Dm1, sD);
        sD = fmaf(Dm2, Dm2, sD); sD = fmaf(Dm3, Dm3, sD);
        float c33 = fmaf(0.5f, sD, D0c * D0c);

        float sBD = Dp0 * Bp0;
        sBD = fmaf(Dp1, Bp1, sBD); sBD = fmaf(Dp2, Bp2, sBD); sBD = fmaf(Dp3, Bp3, sBD);
        sBD = fmaf(Dm0, Bm0, sBD); sBD = fmaf(Dm1, Bm1, sBD);
        sBD = fmaf(Dm2, Bm2, sBD); sBD = fmaf(Dm3, Bm3, sBD);
        float c31 = fmaf(0.5f, sBD, D0c * B0c);

        c00 += DIAG_ADD5; c11 += DIAG_ADD5; c22 += DIAG_ADD5; c33 += DIAG_ADD5;

        // ---- next-step policy (independent of the Cholesky chain below,
        //      lets exp/shuffles overlap the rsqrt chain) ----
        const float u_next = policy_u(n0, n1, n2, n3, wA, muA, LA, wB, muB, LB);

        // ---- reward (closed form): m^T Q m + 0.2 * trace(Q * 5C) ----
        const float q = fmaf(n0, n0, fmaf(n1, n1, fmaf(10.f * n2, n2, n3 * n3)));
        const float tr = c00 + c11 + fmaf(10.f, c22, c33);
        reward -= fmaf(0.2f, tr, q);

        // ---- 4x4 Cholesky via rsqrt (output is already sqrt(5)*S) ----
        const float r0 = rsqrtf(c00);
        S00 = c00 * r0;
        S10 = c10 * r0; S20 = c20 * r0; S30 = c30 * r0;
        const float a11 = fmaf(-S10, S10, c11);
        const float r1 = rsqrtf(a11);
        S11 = a11 * r1;
        S21 = fmaf(-S20, S10, c21) * r1;
        S31 = fmaf(-S30, S10, c31) * r1;
        const float a22 = fmaf(-S21, S21, fmaf(-S20, S20, c22));
        const float r2 = rsqrtf(a22);
        S22 = a22 * r2;
        S32 = fmaf(-S31, S21, fmaf(-S30, S20, c32)) * r2;
        const float a33 = fmaf(-S32, S32, fmaf(-S31, S31, fmaf(-S30, S30, c33)));
        S33 = a33 * rsqrtf(a33);

        m0 = n0; m1 = n1; m2 = n2; m3 = n3;
        u = u_next;
    }

    if (lane == 0) out[0] = reward;
}

extern "C" void kernel_launch(void* const* d_in, const int* in_sizes, int n_in,
                              void* d_out, int out_size) {
    (void)in_sizes; (void)n_in; (void)out_size;
    horizon_reward_kernel<<<1, 32>>>((const float*)d_in[0], (float*)d_out);
}

// round 5
// speedup vs baseline: 5.8855x; 1.0015x over previous
#include <cuda_runtime.h>
#include <math.h>

// HorizonReward: collapsed UT cartpole rollout, f32x2-packed.
// Single warp is FMA-pipe rt2-bound; packed fp32x2 (FFMA2) halves fma-pipe
// instruction count on the +/- sigma-pair sections and the 2-RBF policy pair.
// Math identical to the verified R4 formulation (centered B/D covariance,
// x5-prescaled so chol() yields sqrt(5)*S directly).

typedef unsigned long long u64;

__device__ __forceinline__ u64 pk(float lo, float hi) {
    u64 r; asm("mov.b64 %0,{%1,%2};" : "=l"(r) : "f"(lo), "f"(hi)); return r;
}
__device__ __forceinline__ void upk(u64 a, float& x, float& y) {
    asm("mov.b64 {%0,%1},%2;" : "=f"(x), "=f"(y) : "l"(a));
}
__device__ __forceinline__ u64 sp2(float s) { return pk(s, s); }
__device__ __forceinline__ u64 fma2_(u64 a, u64 b, u64 c) {
    u64 d; asm("fma.rn.f32x2 %0,%1,%2,%3;" : "=l"(d) : "l"(a), "l"(b), "l"(c)); return d;
}
__device__ __forceinline__ u64 mul2_(u64 a, u64 b) {
    u64 d; asm("mul.rn.f32x2 %0,%1,%2;" : "=l"(d) : "l"(a), "l"(b)); return d;
}
__device__ __forceinline__ u64 add2_(u64 a, u64 b) {
    u64 d; asm("add.rn.f32x2 %0,%1,%2;" : "=l"(d) : "l"(a), "l"(b)); return d;
}
__device__ __forceinline__ float rcp_(float x) {
    float r; asm("rcp.approx.f32 %0,%1;" : "=f"(r) : "f"(x)); return r;
}
__device__ __forceinline__ float ex2_(float x) {
    float r; asm("ex2.approx.f32 %0,%1;" : "=f"(r) : "f"(x)); return r;
}

// packed policy: RBF-A in lo lane, RBF-B in hi lane of every f32x2.
__device__ __forceinline__ float policy_u2(
    float n0, float n1, float n2, float n3,
    u64 w2, const u64* nmu2, const u64* L2, u64 NL2E2)
{
    u64 d0 = add2_(sp2(n0), nmu2[0]);
    u64 d1 = add2_(sp2(n1), nmu2[1]);
    u64 d2 = add2_(sp2(n2), nmu2[2]);
    u64 d3 = add2_(sp2(n3), nmu2[3]);
    u64 l0 = mul2_(L2[0], d0);
    l0 = fma2_(L2[4], d1, l0); l0 = fma2_(L2[5], d2, l0); l0 = fma2_(L2[7], d3, l0);
    u64 l1 = mul2_(L2[1], d1); l1 = fma2_(L2[6], d2, l1); l1 = fma2_(L2[8], d3, l1);
    u64 l2 = mul2_(L2[2], d2); l2 = fma2_(L2[9], d3, l2);
    u64 l3 = mul2_(L2[3], d3);
    u64 q = mul2_(l0, l0);
    q = fma2_(l1, l1, q); q = fma2_(l2, l2, q); q = fma2_(l3, l3, q);
    q = mul2_(q, NL2E2);                 // -q * log2(e), both RBFs
    float qa, qb; upk(q, qa, qb);
    float ea = ex2_(qa), eb = ex2_(qb);
    float wa, wb; upk(w2, wa, wb);
    float acc = fmaf(wa, ea, wb * eb);
    #pragma unroll
    for (int o = 16; o > 0; o >>= 1)
        acc += __shfl_xor_sync(0xffffffffu, acc, o);
    return fminf(fmaxf(acc, -10.f), 10.f);
}

__global__ __launch_bounds__(32, 1)
void horizon_reward_kernel(const float* __restrict__ p, float* __restrict__ out)
{
    const int lane = threadIdx.x & 31;

    // ---- policy params, packed (A = RBF lane, B = RBF lane+32; B zero-padded) ----
    u64 w2, nmu2[4], L2[10];
    {
        const int j = lane, j2 = lane + 32;
        const bool hb = (j2 < 50);
        w2 = pk(p[j], hb ? p[j2] : 0.f);
        #pragma unroll
        for (int k = 0; k < 4; ++k)
            nmu2[k] = pk(-p[50 + k * 50 + j], hb ? -p[50 + k * 50 + j2] : 0.f);
        #pragma unroll
        for (int t = 0; t < 10; ++t)
            L2[t] = pk(p[250 + j * 10 + t], hb ? p[250 + j2 * 10 + t] : 0.f);
    }

    const float DT = 0.05f;
    const float W0 = 0.2f, WI = 0.1f;
    const float K1 = 0.05f / 1.1f;
    const float K3 = 0.5f * (4.0f / 3.0f);
    const float K2 = 0.5f * 0.1f / 1.1f;
    const float DIAG_ADD5 = 5.0f * (0.01f * 0.05f + 2.0f * 1e-6f);

    const u64 CPM   = pk(1.f, -1.f);
    const u64 DT2   = sp2(DT);
    const u64 K1_2  = sp2(K1);
    const u64 NK1_2 = sp2(-K1);
    const u64 C98_2 = sp2(9.8f);
    const u64 NM1_2 = sp2(-1.f);
    const u64 NL2E2 = sp2(-1.4426950408889634f);

    // ---- state: mean + scaled Cholesky sqrt(5)*chol(C) ----
    float m0 = 0.f, m1 = 0.f, m2 = 0.1f, m3 = 0.f;
    const float r0i = 2.23606797749979f * 1e-3f;
    float S00 = r0i, S10 = 0.f, S20 = 0.f, S30 = 0.f;
    float S11 = r0i, S21 = 0.f, S31 = 0.f;
    float S22 = r0i, S32 = 0.f;
    float S33 = r0i;

    float u = policy_u2(m0, m1, m2, m3, w2, nmu2, L2, NL2E2);
    float reward = 0.f;

    #pragma unroll 1
    for (int t = 0; t < 60; ++t) {
        const float u_div = u * (1.0f / 1.1f);
        const u64 ud2 = sp2(u_div);

        // ---- scalar angles (7 unique) + MUFU sincos/rcp ----
        const float thp0 = m2 + S20, thm0 = m2 - S20;
        const float thp1 = m2 + S21, thm1 = m2 - S21;
        const float thp2 = m2 + S22, thm2 = m2 - S22;
        float sc_c = __sinf(m2),  cc_c = __cosf(m2);
        float sp0 = __sinf(thp0), cp0 = __cosf(thp0);
        float sm0 = __sinf(thm0), cm0 = __cosf(thm0);
        float sp1 = __sinf(thp1), cp1 = __cosf(thp1);
        float sm1 = __sinf(thm1), cm1 = __cosf(thm1);
        float sp2v = __sinf(thp2), cp2 = __cosf(thp2);
        float sm2v = __sinf(thm2), cm2 = __cosf(thm2);
        const float rdc = rcp_(fmaf(-K2 * cc_c, cc_c, K3));
        const float rp0 = rcp_(fmaf(-K2 * cp0, cp0, K3));
        const float rm0 = rcp_(fmaf(-K2 * cm0, cm0, K3));
        const float rp1 = rcp_(fmaf(-K2 * cp1, cp1, K3));
        const float rm1 = rcp_(fmaf(-K2 * cm1, cm1, K3));
        const float rp2 = rcp_(fmaf(-K2 * cp2, cp2, K3));
        const float rm2 = rcp_(fmaf(-K2 * cm2, cm2, K3));

        // ---- pack per-pair (lo = +col_j, hi = -col_j); pair 3 shares center th ----
        u64 sn2[4], cs2[4], rd2[4];
        sn2[0] = pk(sp0, sm0);  cs2[0] = pk(cp0, cm0);  rd2[0] = pk(rp0, rm0);
        sn2[1] = pk(sp1, sm1);  cs2[1] = pk(cp1, cm1);  rd2[1] = pk(rp1, rm1);
        sn2[2] = pk(sp2v, sm2v); cs2[2] = pk(cp2, cm2); rd2[2] = pk(rp2, rm2);
        sn2[3] = sp2(sc_c);     cs2[3] = sp2(cc_c);     rd2[3] = sp2(rdc);

        // pm pairs (S, -S) and packed thd
        const u64 pmS30 = mul2_(sp2(S30), CPM);
        const u64 pmS31 = mul2_(sp2(S31), CPM);
        const u64 pmS32 = mul2_(sp2(S32), CPM);
        const u64 pmS33 = mul2_(sp2(S33), CPM);
        const u64 pmS10 = mul2_(sp2(S10), CPM);
        const u64 pmS11 = mul2_(sp2(S11), CPM);
        const u64 m3_2 = sp2(m3);
        u64 thd2[4];
        thd2[0] = add2_(pmS30, m3_2);
        thd2[1] = add2_(pmS31, m3_2);
        thd2[2] = add2_(pmS32, m3_2);
        thd2[3] = add2_(pmS33, m3_2);

        // ---- packed dynamics on 4 pairs ----
        u64 xa2[4], ta2[4];
        #pragma unroll
        for (int j = 0; j < 4; ++j) {
            u64 tq   = mul2_(thd2[j], thd2[j]);
            u64 tk   = mul2_(tq, K1_2);
            u64 temp = fma2_(tk, sn2[j], ud2);
            u64 ct   = mul2_(cs2[j], temp);
            u64 g    = mul2_(sn2[j], C98_2);
            u64 num  = fma2_(ct, NM1_2, g);        // 9.8*s - c*temp
            u64 ta   = mul2_(num, rd2[j]);
            u64 tc   = mul2_(ta, cs2[j]);
            ta2[j] = ta;
            xa2[j] = fma2_(tc, NK1_2, temp);       // temp - K1*ta*c
        }
        // center scalar dynamics
        float xac, tac;
        {
            float tmp = fmaf(K1 * m3 * m3, sc_c, u_div);
            tac = (fmaf(-cc_c, tmp, 9.8f * sc_c)) * rdc;
            xac = fmaf(-K1, tac * cc_c, tmp);
        }

        // ---- acceleration means ----
        u64 sx2 = add2_(add2_(xa2[0], xa2[1]), add2_(xa2[2], xa2[3]));
        u64 st2 = add2_(add2_(ta2[0], ta2[1]), add2_(ta2[2], ta2[3]));
        float sxl, sxh, stl, sth;
        upk(sx2, sxl, sxh); upk(st2, stl, sth);
        const float xbar = fmaf(W0, xac, WI * (sxl + sxh));
        const float tbar = fmaf(W0, tac, WI * (stl + sth));

        // next mean
        const float n0 = fmaf(DT, m1, m0);
        const float n1 = fmaf(DT, xbar, m1);
        const float n2 = fmaf(DT, m3, m2);
        const float n3 = fmaf(DT, tbar, m3);

        // ---- centered deviations, packed: B (coord1), D (coord3) ----
        const u64 nxb2 = sp2(-xbar);
        const u64 ntb2 = sp2(-tbar);
        u64 B2[4], D2[4];
        B2[0] = fma2_(add2_(xa2[0], nxb2), DT2, pmS10);
        B2[1] = fma2_(add2_(xa2[1], nxb2), DT2, pmS11);
        B2[2] = mul2_(add2_(xa2[2], nxb2), DT2);
        B2[3] = mul2_(add2_(xa2[3], nxb2), DT2);
        D2[0] = fma2_(add2_(ta2[0], ntb2), DT2, pmS30);
        D2[1] = fma2_(add2_(ta2[1], ntb2), DT2, pmS31);
        D2[2] = fma2_(add2_(ta2[2], ntb2), DT2, pmS32);
        D2[3] = fma2_(add2_(ta2[3], ntb2), DT2, pmS33);
        const float Bc = DT * (xac - xbar);
        const float Dc = DT * (tac - tbar);

        // linear-coord deviations
        const float A0 = fmaf(DT, S10, S00);
        const float A1 = DT * S11;
        const float C0 = fmaf(DT, S30, S20);
        const float C1 = fmaf(DT, S31, S21);
        const float C2 = fmaf(DT, S32, S22);
        const float C3 = DT * S33;

        // ---- covariance (x5 prescaled) ----
        float c00 = fmaf(A1, A1, A0 * A0) + DIAG_ADD5;
        float c20 = fmaf(A1, C1, A0 * C0);
        float c22 = fmaf(C3, C3, fmaf(C2, C2, fmaf(C1, C1, C0 * C0))) + DIAG_ADD5;

        // packed moments
        u64 sBB = mul2_(B2[0], B2[0]);
        sBB = fma2_(B2[1], B2[1], sBB);
        sBB = fma2_(B2[2], B2[2], sBB);
        sBB = fma2_(B2[3], B2[3], sBB);
        u64 sDD = mul2_(D2[0], D2[0]);
        sDD = fma2_(D2[1], D2[1], sDD);
        sDD = fma2_(D2[2], D2[2], sDD);
        sDD = fma2_(D2[3], D2[3], sDD);
        u64 sBD = mul2_(B2[0], D2[0]);
        sBD = fma2_(B2[1], D2[1], sBD);
        sBD = fma2_(B2[2], D2[2], sBD);
        sBD = fma2_(B2[3], D2[3], sBD);
        float bbl, bbh, ddl, ddh, bdl, bdh;
        upk(sBB, bbl, bbh); upk(sDD, ddl, ddh); upk(sBD, bdl, bdh);
        float c11 = fmaf(0.5f, bbl + bbh, Bc * Bc) + DIAG_ADD5;
        float c33 = fmaf(0.5f, ddl + ddh, Dc * Dc) + DIAG_ADD5;
        float c31 = fmaf(0.5f, bdl + bdh, Bc * Dc);

        // g-terms (hi-lo differences) for cross covariances with linear coords
        float bp0, bm0, bp1, bm1, bp2, bm2, bp3, bm3;
        upk(B2[0], bp0, bm0); upk(B2[1], bp1, bm1);
        upk(B2[2], bp2, bm2); upk(B2[3], bp3, bm3);
        float dp0, dm0, dp1, dm1, dp2, dm2, dp3, dm3;
        upk(D2[0], dp0, dm0); upk(D2[1], dp1, dm1);
        upk(D2[2], dp2, dm2); upk(D2[3], dp3, dm3);
        const float gB0 = bp0 - bm0, gB1 = bp1 - bm1, gB2 = bp2 - bm2, gB3 = bp3 - bm3;
        const float gD0 = dp0 - dm0, gD1 = dp1 - dm1, gD2 = dp2 - dm2, gD3 = dp3 - dm3;
        const float c10 = 0.5f * fmaf(A1, gB1, A0 * gB0);
        const float c30 = 0.5f * fmaf(A1, gD1, A0 * gD0);
        const float c21 = 0.5f * fmaf(C3, gB3, fmaf(C2, gB2, fmaf(C1, gB1, C0 * gB0)));
        const float c32 = 0.5f * fmaf(C3, gD3, fmaf(C2, gD2, fmaf(C1, gD1, C0 * gD0)));

        // ---- next-step policy (overlaps Cholesky chain) ----
        const float u_next = policy_u2(n0, n1, n2, n3, w2, nmu2, L2, NL2E2);

        // ---- reward: m^T Q m + 0.2 * trace(Q * 5C) ----
        const float q = fmaf(n0, n0, fmaf(n1, n1, fmaf(10.f * n2, n2, n3 * n3)));
        const float tr = c00 + c11 + fmaf(10.f, c22, c33);
        reward -= fmaf(0.2f, tr, q);

        // ---- 4x4 Cholesky via rsqrt ----
        const float r0 = rsqrtf(c00);
        S00 = c00 * r0;
        S10 = c10 * r0; S20 = c20 * r0; S30 = c30 * r0;
        const float a11 = fmaf(-S10, S10, c11);
        const float r1 = rsqrtf(a11);
        S11 = a11 * r1;
        S21 = fmaf(-S20, S10, c21) * r1;
        S31 = fmaf(-S30, S10, c31) * r1;
        const float a22 = fmaf(-S21, S21, fmaf(-S20, S20, c22));
        const float r2 = rsqrtf(a22);
        S22 = a22 * r2;
        S32 = fmaf(-S31, S21, fmaf(-S30, S20, c32)) * r2;
        const float a33 = fmaf(-S32, S32, fmaf(-S31, S31, fmaf(-S30, S30, c33)));
        S33 = a33 * rsqrtf(a33);

        m0 = n0; m1 = n1; m2 = n2; m3 = n3;
        u = u_next;
    }

    if (lane == 0) out[0] = reward;
}

extern "C" void kernel_launch(void* const* d_in, const int* in_sizes, int n_in,
                              void* d_out, int out_size) {
    (void)in_sizes; (void)n_in; (void)out_size;
    horizon_reward_kernel<<<1, 32>>>((const float*)d_in[0], (float*)d_out);
}